// round 16
// baseline (speedup 1.0000x reference)
#include <cuda_runtime.h>
#include <cuda_fp16.h>
#include <cstdint>

#define F_IN  512
#define F_OUT 256
#define MAX_N 100000
#define MAX_E 3200000

// ---------------- device scratch -------------------------------------------
__device__ __half g_supportH[(size_t)MAX_N * F_OUT];        // X @ W  (fp16, 51 MB)
__device__ __half g_Wh[(size_t)F_IN * F_OUT];               // fp16(W), converted once
__device__ int    g_count[MAX_N];
__device__ int    g_rowptr[MAX_N + 1];
__device__ int    g_wofs[MAX_N];
__device__ int2   g_edges[MAX_E];

// ---------------- PTX helpers ----------------------------------------------
__device__ __forceinline__ uint32_t smem_u32(const void* p) {
    uint32_t a;
    asm("{ .reg .u64 t; cvta.to.shared.u64 t, %1; cvt.u32.u64 %0, t; }"
        : "=r"(a) : "l"(p));
    return a;
}

#define LDSM_X4(r0, r1, r2, r3, addr) \
    asm volatile("ldmatrix.sync.aligned.m8n8.x4.shared.b16 {%0,%1,%2,%3}, [%4];" \
                 : "=r"(r0), "=r"(r1), "=r"(r2), "=r"(r3) : "r"(addr))

#define LDSM_X4_T(r0, r1, r2, r3, addr) \
    asm volatile("ldmatrix.sync.aligned.m8n8.x4.trans.shared.b16 {%0,%1,%2,%3}, [%4];" \
                 : "=r"(r0), "=r"(r1), "=r"(r2), "=r"(r3) : "r"(addr))

#define MMA_F16(d0, d1, d2, d3, a0, a1, a2, a3, b0, b1) \
    asm volatile("mma.sync.aligned.m16n8k16.row.col.f32.f16.f16.f32 " \
                 "{%0,%1,%2,%3}, {%4,%5,%6,%7}, {%8,%9}, {%0,%1,%2,%3};" \
                 : "+f"(d0), "+f"(d1), "+f"(d2), "+f"(d3) \
                 : "r"(a0), "r"(a1), "r"(a2), "r"(a3), "r"(b0), "r"(b1))

#define CP_ASYNC16(smem, gmem) \
    asm volatile("cp.async.ca.shared.global [%0], [%1], 16;" \
                 :: "r"((uint32_t)(smem)), "l"(gmem) : "memory")
#define CP_COMMIT()  asm volatile("cp.async.commit_group;" ::: "memory")
#define CP_WAIT0()   asm volatile("cp.async.wait_group 0;" ::: "memory")

// fp32x4 -> f16x4 packed as uint2 (rn — identical rounding to prior rounds)
__device__ __forceinline__ uint2 pack4h(float4 v) {
    __half2 p01 = __floats2half2_rn(v.x, v.y);
    __half2 p23 = __floats2half2_rn(v.z, v.w);
    uint2 r;
    r.x = *(uint32_t*)&p01;  r.y = *(uint32_t*)&p23;
    return r;
}

// ---------------------------------------------------------------------------
// Kernel 0: one-shot W fp32 -> fp16 conversion
// ---------------------------------------------------------------------------
__global__ __launch_bounds__(256)
void gcn_convw_kernel(const float* __restrict__ W, __half* __restrict__ Wh) {
    int i4 = blockIdx.x * blockDim.x + threadIdx.x;
    float4 v = __ldg((const float4*)W + i4);
    *(uint2*)((__half*)Wh + (size_t)i4 * 4) = pack4h(v);
}

// ---------------------------------------------------------------------------
// Kernel 1: single-term fp16 HMMA GEMM over ONE 128-col N-tile.
// 128 threads, 4 warps, warp tile 64x64 (LDSM bytes/MMA 192 -> 128).
//   A: LDG fp32 reg-prefetch (tile t+1 before compute t) -> STS fp16
//   B: cp.async fp16 gmem->smem, double-buffered
// K-tile 32, fp32 accum.
// ---------------------------------------------------------------------------
#define SA_STR 40
#define SB_STR 136
#define BBUF   (32 * SB_STR)     // halves per B buffer

__global__ __launch_bounds__(128, 2)
void gcn_mma_gemm(const float* __restrict__ A,      // [N, 512] fp32
                  const __half* __restrict__ Wh,    // [512, 256] fp16
                  __half* __restrict__ C,           // [N, 256] fp16
                  int Nn, int ncol0) {
    __shared__ __align__(16) __half sA[128 * SA_STR];
    __shared__ __align__(16) __half sB[2 * BBUF];

    const int tid   = threadIdx.x;
    const int lane  = tid & 31;
    const int wid   = tid >> 5;          // 0..3
    const int warpM = wid & 1;           // m offset 64*warpM
    const int warpN = wid >> 1;          // n offset 64*warpN
    const int m0    = blockIdx.y * 128;
    const int n0    = ncol0;

    const uint32_t sA_b = smem_u32(sA);
    const uint32_t sB_b = smem_u32(sB);

    float acc[4][8][4];
    #pragma unroll
    for (int i = 0; i < 4; i++)
        #pragma unroll
        for (int j = 0; j < 8; j++)
            #pragma unroll
            for (int k = 0; k < 4; k++) acc[i][j][k] = 0.0f;

    // gmem->smem mappings (128 threads)
    const int ar = tid;                  // A row 0..127, 8 float4 (k 0..31)
    const int kr = tid >> 2;             // B k-row 0..31
    const int nc = (tid & 3) * 32;       // B n offset (halves), 64B each
    const int grow = m0 + ar;

    // ldmatrix address components
    const uint32_t a_rowb = (uint32_t)(warpM * 64 + (lane & 15));  // + mf*16
    const uint32_t a_colb = (uint32_t)((lane >> 4) * 8);
    const uint32_t b_k    = (uint32_t)(((lane >> 3) & 1) * 8 + (lane & 7));
    const uint32_t b_n    = (uint32_t)(warpN * 64 + (lane >> 4) * 8);

    const uint32_t bdst = sB_b + (uint32_t)((kr * SB_STR + nc) * 2);

    auto ldgA = [&](int k0, float4* av) {
        const float4* ap = (const float4*)(A + (size_t)grow * F_IN + k0);
        #pragma unroll
        for (int i = 0; i < 8; i++)
            av[i] = (grow < Nn) ? __ldg(ap + i) : make_float4(0.f, 0.f, 0.f, 0.f);
    };
    auto stsA = [&](const float4* av) {
        #pragma unroll
        for (int i = 0; i < 8; i++)
            *(uint2*)(sA + ar * SA_STR + i * 4) = pack4h(av[i]);
    };
    auto cpB = [&](int k0, int buf) {
        const __half* gp = Wh + (size_t)(k0 + kr) * F_OUT + n0 + nc;
        uint32_t d = bdst + (uint32_t)(buf * BBUF * 2);
        CP_ASYNC16(d,      gp);
        CP_ASYNC16(d + 16, gp + 8);
        CP_ASYNC16(d + 32, gp + 16);
        CP_ASYNC16(d + 48, gp + 24);
        CP_COMMIT();
    };

    // ---- prologue: tile 0 ----
    {
        float4 av[8];
        ldgA(0, av);
        cpB(0, 0);
        stsA(av);
        CP_WAIT0();
    }
    __syncthreads();

    const int NT = F_IN / 32;    // 16
    for (int t = 0; t < NT; t++) {
        // issue next tile's loads before compute
        float4 av[8];
        if (t + 1 < NT) {
            ldgA((t + 1) * 32, av);
            cpB((t + 1) * 32, (t + 1) & 1);
        }

        // ---- compute tile t ----
        const uint32_t bbase = sB_b + (uint32_t)((t & 1) * BBUF * 2);
        #pragma unroll
        for (int ks = 0; ks < 2; ks++) {
            const uint32_t boffk = ((b_k + (uint32_t)(ks * 16)) * SB_STR + b_n) * 2;

            uint32_t a[16], b[16];

            #pragma unroll
            for (int mf = 0; mf < 4; mf++) {
                const uint32_t aoff =
                    ((a_rowb + (uint32_t)(mf * 16)) * SA_STR +
                     (uint32_t)(ks * 16) + a_colb) * 2;
                LDSM_X4(a[4 * mf], a[4 * mf + 1], a[4 * mf + 2], a[4 * mf + 3],
                        sA_b + aoff);
            }
            #pragma unroll
            for (int lg = 0; lg < 4; lg++)
                LDSM_X4_T(b[4 * lg], b[4 * lg + 1], b[4 * lg + 2], b[4 * lg + 3],
                          bbase + boffk + (uint32_t)(lg * 16) * 2);

            #pragma unroll
            for (int mf = 0; mf < 4; mf++)
                #pragma unroll
                for (int nf = 0; nf < 8; nf++)
                    MMA_F16(acc[mf][nf][0], acc[mf][nf][1], acc[mf][nf][2], acc[mf][nf][3],
                            a[4 * mf], a[4 * mf + 1], a[4 * mf + 2], a[4 * mf + 3],
                            b[2 * nf], b[2 * nf + 1]);
        }
        __syncthreads();               // done reading sA (and old B buffer)

        if (t + 1 < NT) {
            stsA(av);                  // overwrite sA with tile t+1
            CP_WAIT0();                // B(t+1) landed in the other buffer
            __syncthreads();
        }
    }

    // ---- epilogue: fp16 stores ----
    const int g  = lane >> 2;
    const int tg = lane & 3;
    #pragma unroll
    for (int mf = 0; mf < 4; mf++) {
        #pragma unroll
        for (int nf = 0; nf < 8; nf++) {
            const int col  = n0 + warpN * 64 + nf * 8 + tg * 2;
            const int row0 = m0 + warpM * 64 + mf * 16 + g;
            const int row1 = row0 + 8;
            if (row0 < Nn)
                *(__half2*)(C + (size_t)row0 * F_OUT + col) =
                    __floats2half2_rn(acc[mf][nf][0], acc[mf][nf][1]);
            if (row1 < Nn)
                *(__half2*)(C + (size_t)row1 * F_OUT + col) =
                    __floats2half2_rn(acc[mf][nf][2], acc[mf][nf][3]);
        }
    }
}

// ---------------------------------------------------------------------------
// Kernel 2a: histogram of destination rows
// ---------------------------------------------------------------------------
__global__ __launch_bounds__(256)
void gcn_hist_kernel(const int* __restrict__ row, int E) {
    int e = blockIdx.x * blockDim.x + threadIdx.x;
    if (e < E) atomicAdd(&g_count[row[e]], 1);
}

// ---------------------------------------------------------------------------
// Kernel 2b: exclusive scan -> rowptr + cursors (single block)
// ---------------------------------------------------------------------------
__global__ __launch_bounds__(1024)
void gcn_scan_kernel(int n) {
    __shared__ int warp_sums[32];
    __shared__ int s_carry;
    const int tid = threadIdx.x, lane = tid & 31, wid = tid >> 5;
    if (tid == 0) s_carry = 0;
    __syncthreads();
    for (int base = 0; base < n; base += 1024) {
        int i = base + tid;
        int v = (i < n) ? g_count[i] : 0;
        int x = v;
        #pragma unroll
        for (int d = 1; d < 32; d <<= 1) {
            int y = __shfl_up_sync(0xffffffff, x, d);
            if (lane >= d) x += y;
        }
        if (lane == 31) warp_sums[wid] = x;
        __syncthreads();
        if (wid == 0) {
            int tsum = warp_sums[lane];
            #pragma unroll
            for (int d = 1; d < 32; d <<= 1) {
                int y = __shfl_up_sync(0xffffffff, tsum, d);
                if (lane >= d) tsum += y;
            }
            warp_sums[lane] = tsum;
        }
        __syncthreads();
        int warp_off = (wid > 0) ? warp_sums[wid - 1] : 0;
        int excl = s_carry + warp_off + x - v;
        if (i < n) { g_rowptr[i] = excl; g_wofs[i] = excl; }
        __syncthreads();
        if (tid == 0) s_carry += warp_sums[31];
        __syncthreads();
    }
    if (threadIdx.x == 0) g_rowptr[n] = s_carry;
}

// ---------------------------------------------------------------------------
// Kernel 2c: scatter edges into row-sorted order
// ---------------------------------------------------------------------------
__global__ __launch_bounds__(256)
void gcn_scatter_kernel(const int* __restrict__ row,
                        const int* __restrict__ col,
                        const float* __restrict__ val, int E) {
    int e = blockIdx.x * blockDim.x + threadIdx.x;
    if (e >= E) return;
    int r = row[e];
    int p = atomicAdd(&g_wofs[r], 1);
    g_edges[p] = make_int2(col[e], __float_as_int(val[e]));
}

// ---------------------------------------------------------------------------
// Kernel 3: CSR segment reduction over ONE 128-col half of fp16 support.
// Warp-per-row, FULL grid. 16-edge unroll (16 LDG.64/lane in flight).
// ---------------------------------------------------------------------------
__device__ __forceinline__ void acc_edge2(float acc[4], uint2 v, float wv) {
    const __half2* h = (const __half2*)&v;
    float2 f0 = __half22float2(h[0]);
    float2 f1 = __half22float2(h[1]);
    acc[0] = fmaf(wv, f0.x, acc[0]);
    acc[1] = fmaf(wv, f0.y, acc[1]);
    acc[2] = fmaf(wv, f1.x, acc[2]);
    acc[3] = fmaf(wv, f1.y, acc[3]);
}

__global__ __launch_bounds__(256)
void gcn_csr_kernel(const __half* __restrict__ support,
                    const float* __restrict__ bias,
                    float* __restrict__ out, int N, int coff) {
    const int lane   = threadIdx.x & 31;
    const int warp0  = (blockIdx.x * blockDim.x + threadIdx.x) >> 5;
    const int nwarps = (gridDim.x * blockDim.x) >> 5;

    const float4 bi = __ldg((const float4*)(bias + coff) + lane);

    for (int w = warp0; w < N; w += nwarps) {
        int s = g_rowptr[w];
        int e = g_rowptr[w + 1];

        float acc[4] = {0.f, 0.f, 0.f, 0.f};

        int i = s;
        for (; i + 16 <= e; i += 16) {
            int2  cv[16];
            uint2 v[16];
            #pragma unroll
            for (int u = 0; u < 16; u++) cv[u] = g_edges[i + u];
            #pragma unroll
            for (int u = 0; u < 16; u++)
                v[u] = __ldg((const uint2*)(support + (size_t)cv[u].x * F_OUT + coff) + lane);
            #pragma unroll
            for (int u = 0; u < 16; u++)
                acc_edge2(acc, v[u], __int_as_float(cv[u].y));
        }
        for (; i + 4 <= e; i += 4) {
            int2  cv[4];
            uint2 v[4];
            #pragma unroll
            for (int u = 0; u < 4; u++) cv[u] = g_edges[i + u];
            #pragma unroll
            for (int u = 0; u < 4; u++)
                v[u] = __ldg((const uint2*)(support + (size_t)cv[u].x * F_OUT + coff) + lane);
            #pragma unroll
            for (int u = 0; u < 4; u++)
                acc_edge2(acc, v[u], __int_as_float(cv[u].y));
        }
        for (; i < e; i++) {
            int2 cv = g_edges[i];
            uint2 v = __ldg((const uint2*)(support + (size_t)cv.x * F_OUT + coff) + lane);
            acc_edge2(acc, v, __int_as_float(cv.y));
        }

        float4 o;
        o.x = __fdiv_rn(rintf(acc[0] * 1000.0f), 1000.0f) + bi.x;
        o.y = __fdiv_rn(rintf(acc[1] * 1000.0f), 1000.0f) + bi.y;
        o.z = __fdiv_rn(rintf(acc[2] * 1000.0f), 1000.0f) + bi.z;
        o.w = __fdiv_rn(rintf(acc[3] * 1000.0f), 1000.0f) + bi.w;

        *(float4*)(out + (size_t)w * F_OUT + coff + lane * 4) = o;
    }
}

// ---------------------------------------------------------------------------
// Launch — R10 schedule (proven best) + W pre-conversion:
//   main: convW -> GEMM(cols 0-127) -> GEMM(cols 128-255) -> CSR(cols 128-255)
//   s1:   CSR build chain (hidden under GEMM0)
//   s2:   CSR(cols 0-127) overlapping GEMM(cols 128-255)
// ---------------------------------------------------------------------------
extern "C" void kernel_launch(void* const* d_in, const int* in_sizes, int n_in,
                              void* d_out, int out_size) {
    const float* x        = (const float*)d_in[0];
    const float* weight   = (const float*)d_in[1];
    const float* bias     = (const float*)d_in[2];
    const float* edge_val = (const float*)d_in[3];
    const int*   row      = (const int*)d_in[4];
    const int*   col      = (const int*)d_in[5];
    float*       out      = (float*)d_out;

    const int N = in_sizes[0] / F_IN;
    const int E = in_sizes[3];

    __half* support;
    cudaGetSymbolAddress((void**)&support, g_supportH);
    __half* wh;
    cudaGetSymbolAddress((void**)&wh, g_Wh);
    int* count_ptr;
    cudaGetSymbolAddress((void**)&count_ptr, g_count);

    static cudaStream_t s1 = nullptr, s2 = nullptr;
    static cudaEvent_t ev_fork = nullptr, ev_join = nullptr;
    static cudaEvent_t ev_g0 = nullptr, ev_c0 = nullptr;
    static bool init_done = false;
    if (!init_done) {
        cudaStreamCreateWithFlags(&s1, cudaStreamNonBlocking);
        cudaStreamCreateWithFlags(&s2, cudaStreamNonBlocking);
        cudaEventCreateWithFlags(&ev_fork, cudaEventDisableTiming);
        cudaEventCreateWithFlags(&ev_join, cudaEventDisableTiming);
        cudaEventCreateWithFlags(&ev_g0, cudaEventDisableTiming);
        cudaEventCreateWithFlags(&ev_c0, cudaEventDisableTiming);
        init_done = true;
    }

    const int eblocks    = (E + 255) / 256;
    const int csr_blocks = (N * 32 + 255) / 256;   // full warp-per-row grid
    const dim3 gemm_grid(1, (N + 127) / 128);

    // fork: CSR build chain on s1
    cudaEventRecord(ev_fork, 0);
    cudaStreamWaitEvent(s1, ev_fork, 0);

    cudaMemsetAsync(count_ptr, 0, (size_t)N * sizeof(int), s1);
    gcn_hist_kernel<<<eblocks, 256, 0, s1>>>(row, E);
    gcn_scan_kernel<<<1, 1024, 0, s1>>>(N);
    gcn_scatter_kernel<<<eblocks, 256, 0, s1>>>(row, col, edge_val, E);
    cudaEventRecord(ev_join, s1);

    // W -> fp16 (tiny), then GEMM halves on main
    gcn_convw_kernel<<<(F_IN * F_OUT / 4 + 255) / 256, 256>>>(weight, wh);

    gcn_mma_gemm<<<gemm_grid, 128>>>(x, wh, support, N, 0);
    cudaEventRecord(ev_g0, 0);

    gcn_mma_gemm<<<gemm_grid, 128>>>(x, wh, support, N, 128);

    // CSR half 0 on s2: needs GEMM0 + sorted edges; overlaps GEMM1
    cudaStreamWaitEvent(s2, ev_g0, 0);
    cudaStreamWaitEvent(s2, ev_join, 0);
    gcn_csr_kernel<<<csr_blocks, 256, 0, s2>>>(support, bias, out, N, 0);
    cudaEventRecord(ev_c0, s2);

    // CSR half 1 on main: needs GEMM1 (stream order) + sorted edges
    cudaStreamWaitEvent(0, ev_join, 0);
    gcn_csr_kernel<<<csr_blocks, 256>>>(support, bias, out, N, 128);

    // join s2 back into main
    cudaStreamWaitEvent(0, ev_c0, 0);
}

// round 17
// speedup vs baseline: 1.0629x; 1.0629x over previous
#include <cuda_runtime.h>
#include <cuda_fp16.h>
#include <cstdint>

#define F_IN  512
#define F_OUT 256
#define MAX_N 100000
#define MAX_E 3200000

// ---------------- device scratch -------------------------------------------
__device__ __half g_supportH[(size_t)MAX_N * F_OUT];        // X @ W  (fp16, 51 MB)
__device__ __half g_Ah[(size_t)MAX_N * F_IN];               // fp16(X) (102 MB)
__device__ __half g_Wh[(size_t)F_IN * F_OUT];               // fp16(W)
__device__ int    g_count[MAX_N];
__device__ int    g_rowptr[MAX_N + 1];
__device__ int    g_wofs[MAX_N];
__device__ int2   g_edges[MAX_E];

// ---------------- PTX helpers ----------------------------------------------
__device__ __forceinline__ uint32_t smem_u32(const void* p) {
    uint32_t a;
    asm("{ .reg .u64 t; cvta.to.shared.u64 t, %1; cvt.u32.u64 %0, t; }"
        : "=r"(a) : "l"(p));
    return a;
}

#define LDSM_X4(r0, r1, r2, r3, addr) \
    asm volatile("ldmatrix.sync.aligned.m8n8.x4.shared.b16 {%0,%1,%2,%3}, [%4];" \
                 : "=r"(r0), "=r"(r1), "=r"(r2), "=r"(r3) : "r"(addr))

#define LDSM_X4_T(r0, r1, r2, r3, addr) \
    asm volatile("ldmatrix.sync.aligned.m8n8.x4.trans.shared.b16 {%0,%1,%2,%3}, [%4];" \
                 : "=r"(r0), "=r"(r1), "=r"(r2), "=r"(r3) : "r"(addr))

#define MMA_F16(d0, d1, d2, d3, a0, a1, a2, a3, b0, b1) \
    asm volatile("mma.sync.aligned.m16n8k16.row.col.f32.f16.f16.f32 " \
                 "{%0,%1,%2,%3}, {%4,%5,%6,%7}, {%8,%9}, {%0,%1,%2,%3};" \
                 : "+f"(d0), "+f"(d1), "+f"(d2), "+f"(d3) \
                 : "r"(a0), "r"(a1), "r"(a2), "r"(a3), "r"(b0), "r"(b1))

#define CP_ASYNC16(smem, gmem) \
    asm volatile("cp.async.ca.shared.global [%0], [%1], 16;" \
                 :: "r"((uint32_t)(smem)), "l"(gmem) : "memory")
#define CP_COMMIT()   asm volatile("cp.async.commit_group;" ::: "memory")
#define CP_WAIT(n)    asm volatile("cp.async.wait_group %0;" :: "n"(n) : "memory")

// fp32x4 -> f16x4 packed as uint2 (rn — identical rounding to prior rounds)
__device__ __forceinline__ uint2 pack4h(float4 v) {
    __half2 p01 = __floats2half2_rn(v.x, v.y);
    __half2 p23 = __floats2half2_rn(v.z, v.w);
    uint2 r;
    r.x = *(uint32_t*)&p01;  r.y = *(uint32_t*)&p23;
    return r;
}

// ---------------------------------------------------------------------------
// Kernel 0a/0b: one-shot fp32 -> fp16 conversions (W tiny, A 205->102 MB)
// ---------------------------------------------------------------------------
__global__ __launch_bounds__(256)
void gcn_conv_kernel(const float* __restrict__ src, __half* __restrict__ dst,
                     int n4) {
    int i4 = blockIdx.x * blockDim.x + threadIdx.x;
    if (i4 >= n4) return;
    float4 v = __ldg((const float4*)src + i4);
    *(uint2*)(dst + (size_t)i4 * 4) = pack4h(v);
}

// ---------------------------------------------------------------------------
// Kernel 1: fp16 HMMA GEMM over ONE 128-col N-tile, all-cp.async.
// CTA 128x128, 256 threads, 8 warps (4M x 2N), warp tile 32x64 (R14 mapping).
// A and B both fp16 in gmem; double-buffered cp.async; hot loop = LDSM + MMA.
// ---------------------------------------------------------------------------
#define SA_STR 40
#define SB_STR 136
#define ABUF   (128 * SA_STR)    // halves per A buffer
#define BBUF   (32 * SB_STR)     // halves per B buffer

__global__ __launch_bounds__(256, 2)
void gcn_mma_gemm(const __half* __restrict__ Ah,    // [N, 512] fp16
                  const __half* __restrict__ Wh,    // [512, 256] fp16
                  __half* __restrict__ C,           // [N, 256] fp16
                  int Nn, int ncol0) {
    __shared__ __align__(16) __half sA[2 * ABUF];
    __shared__ __align__(16) __half sB[2 * BBUF];

    const int tid   = threadIdx.x;
    const int lane  = tid & 31;
    const int wid   = tid >> 5;
    const int warpM = wid & 3;
    const int warpN = wid >> 2;
    const int m0    = blockIdx.y * 128;
    const int n0    = ncol0;

    const uint32_t sA_b = smem_u32(sA);
    const uint32_t sB_b = smem_u32(sB);

    float acc[2][8][4];
    #pragma unroll
    for (int i = 0; i < 2; i++)
        #pragma unroll
        for (int j = 0; j < 8; j++)
            #pragma unroll
            for (int k = 0; k < 4; k++) acc[i][j][k] = 0.0f;

    // cp.async mappings
    // A: 128 rows x 32 halves (64B) per tile = 512 x 16B chunks; 2 per thread
    const int a_row  = tid >> 1;                 // 0..127
    const int a_half = (tid & 1) * 16;           // halves offset 0/16
    const int grow   = m0 + a_row;
    // B: 32 k-rows x 128 halves = 256 x 16B chunks; 2 per thread (R14 mapping)
    const int kr = tid >> 3;                     // 0..31
    const int nc = (tid & 7) * 16;               // halves offset 0..112

    const uint32_t adst = sA_b + (uint32_t)((a_row * SA_STR + a_half) * 2);
    const uint32_t bdst = sB_b + (uint32_t)((kr * SB_STR + nc) * 2);

    // ldmatrix address components (R14 mapping)
    const uint32_t am_row = (uint32_t)(warpM * 32 + (lane & 15));
    const uint32_t am_col = (uint32_t)((lane >> 4) * 8);
    const uint32_t b_k    = (uint32_t)(((lane >> 3) & 1) * 8 + (lane & 7));
    const uint32_t b_n    = (uint32_t)(warpN * 64 + (lane >> 4) * 8);

    auto cp_tile = [&](int k0, int buf) {
        // A chunk (guard OOB rows with explicit zero stores)
        uint32_t da = adst + (uint32_t)(buf * ABUF * 2);
        if (grow < Nn) {
            const __half* ga = Ah + (size_t)grow * F_IN + k0 + a_half;
            CP_ASYNC16(da,      ga);
            CP_ASYNC16(da + 16, ga + 8);
        } else {
            *(uint4*)(sA + buf * ABUF + a_row * SA_STR + a_half)     = make_uint4(0, 0, 0, 0);
            *(uint4*)(sA + buf * ABUF + a_row * SA_STR + a_half + 8) = make_uint4(0, 0, 0, 0);
        }
        // B chunks
        const __half* gb = Wh + (size_t)(k0 + kr) * F_OUT + n0 + nc;
        uint32_t db = bdst + (uint32_t)(buf * BBUF * 2);
        CP_ASYNC16(db,      gb);
        CP_ASYNC16(db + 16, gb + 8);
        CP_COMMIT();
    };

    // ---- prologue ----
    cp_tile(0, 0);

    const int NT = F_IN / 32;    // 16
    for (int t = 0; t < NT; t++) {
        if (t + 1 < NT) cp_tile((t + 1) * 32, (t + 1) & 1);

        if (t + 1 < NT) { CP_WAIT(1); } else { CP_WAIT(0); }
        __syncthreads();                       // tile t resident for all warps

        const uint32_t abase = sA_b + (uint32_t)((t & 1) * ABUF * 2);
        const uint32_t bbase = sB_b + (uint32_t)((t & 1) * BBUF * 2);
        #pragma unroll
        for (int ks = 0; ks < 2; ks++) {
            const uint32_t aoff0 = (am_row * SA_STR + (uint32_t)(ks * 16) + am_col) * 2;
            const uint32_t aoff1 = aoff0 + 16 * SA_STR * 2;
            const uint32_t boffk = ((b_k + (uint32_t)(ks * 16)) * SB_STR + b_n) * 2;

            uint32_t a[8], b[16];

            LDSM_X4(a[0], a[1], a[2], a[3], abase + aoff0);
            LDSM_X4(a[4], a[5], a[6], a[7], abase + aoff1);
            #pragma unroll
            for (int lg = 0; lg < 4; lg++)
                LDSM_X4_T(b[4 * lg], b[4 * lg + 1], b[4 * lg + 2], b[4 * lg + 3],
                          bbase + boffk + (uint32_t)(lg * 16) * 2);

            #pragma unroll
            for (int mf = 0; mf < 2; mf++)
                #pragma unroll
                for (int nf = 0; nf < 8; nf++)
                    MMA_F16(acc[mf][nf][0], acc[mf][nf][1], acc[mf][nf][2], acc[mf][nf][3],
                            a[4 * mf], a[4 * mf + 1], a[4 * mf + 2], a[4 * mf + 3],
                            b[2 * nf], b[2 * nf + 1]);
        }
        __syncthreads();   // all warps done reading buf before cp(t+2) targets it
    }

    // ---- epilogue: fp16 stores ----
    const int g  = lane >> 2;
    const int tg = lane & 3;
    #pragma unroll
    for (int mf = 0; mf < 2; mf++) {
        #pragma unroll
        for (int nf = 0; nf < 8; nf++) {
            const int col  = n0 + warpN * 64 + nf * 8 + tg * 2;
            const int row0 = m0 + warpM * 32 + mf * 16 + g;
            const int row1 = row0 + 8;
            if (row0 < Nn)
                *(__half2*)(C + (size_t)row0 * F_OUT + col) =
                    __floats2half2_rn(acc[mf][nf][0], acc[mf][nf][1]);
            if (row1 < Nn)
                *(__half2*)(C + (size_t)row1 * F_OUT + col) =
                    __floats2half2_rn(acc[mf][nf][2], acc[mf][nf][3]);
        }
    }
}

// ---------------------------------------------------------------------------
// Kernel 2a: histogram of destination rows
// ---------------------------------------------------------------------------
__global__ __launch_bounds__(256)
void gcn_hist_kernel(const int* __restrict__ row, int E) {
    int e = blockIdx.x * blockDim.x + threadIdx.x;
    if (e < E) atomicAdd(&g_count[row[e]], 1);
}

// ---------------------------------------------------------------------------
// Kernel 2b: exclusive scan -> rowptr + cursors (single block)
// ---------------------------------------------------------------------------
__global__ __launch_bounds__(1024)
void gcn_scan_kernel(int n) {
    __shared__ int warp_sums[32];
    __shared__ int s_carry;
    const int tid = threadIdx.x, lane = tid & 31, wid = tid >> 5;
    if (tid == 0) s_carry = 0;
    __syncthreads();
    for (int base = 0; base < n; base += 1024) {
        int i = base + tid;
        int v = (i < n) ? g_count[i] : 0;
        int x = v;
        #pragma unroll
        for (int d = 1; d < 32; d <<= 1) {
            int y = __shfl_up_sync(0xffffffff, x, d);
            if (lane >= d) x += y;
        }
        if (lane == 31) warp_sums[wid] = x;
        __syncthreads();
        if (wid == 0) {
            int tsum = warp_sums[lane];
            #pragma unroll
            for (int d = 1; d < 32; d <<= 1) {
                int y = __shfl_up_sync(0xffffffff, tsum, d);
                if (lane >= d) tsum += y;
            }
            warp_sums[lane] = tsum;
        }
        __syncthreads();
        int warp_off = (wid > 0) ? warp_sums[wid - 1] : 0;
        int excl = s_carry + warp_off + x - v;
        if (i < n) { g_rowptr[i] = excl; g_wofs[i] = excl; }
        __syncthreads();
        if (tid == 0) s_carry += warp_sums[31];
        __syncthreads();
    }
    if (threadIdx.x == 0) g_rowptr[n] = s_carry;
}

// ---------------------------------------------------------------------------
// Kernel 2c: scatter edges into row-sorted order
// ---------------------------------------------------------------------------
__global__ __launch_bounds__(256)
void gcn_scatter_kernel(const int* __restrict__ row,
                        const int* __restrict__ col,
                        const float* __restrict__ val, int E) {
    int e = blockIdx.x * blockDim.x + threadIdx.x;
    if (e >= E) return;
    int r = row[e];
    int p = atomicAdd(&g_wofs[r], 1);
    g_edges[p] = make_int2(col[e], __float_as_int(val[e]));
}

// ---------------------------------------------------------------------------
// Kernel 3: CSR segment reduction over ONE 128-col half of fp16 support.
// Warp-per-row, FULL grid, 8-edge unroll (R14 proven config).
// ---------------------------------------------------------------------------
__device__ __forceinline__ void acc_edge2(float acc[4], uint2 v, float wv) {
    const __half2* h = (const __half2*)&v;
    float2 f0 = __half22float2(h[0]);
    float2 f1 = __half22float2(h[1]);
    acc[0] = fmaf(wv, f0.x, acc[0]);
    acc[1] = fmaf(wv, f0.y, acc[1]);
    acc[2] = fmaf(wv, f1.x, acc[2]);
    acc[3] = fmaf(wv, f1.y, acc[3]);
}

__global__ __launch_bounds__(256)
void gcn_csr_kernel(const __half* __restrict__ support,
                    const float* __restrict__ bias,
                    float* __restrict__ out, int N, int coff) {
    const int lane   = threadIdx.x & 31;
    const int warp0  = (blockIdx.x * blockDim.x + threadIdx.x) >> 5;
    const int nwarps = (gridDim.x * blockDim.x) >> 5;

    const float4 bi = __ldg((const float4*)(bias + coff) + lane);

    for (int w = warp0; w < N; w += nwarps) {
        int s = g_rowptr[w];
        int e = g_rowptr[w + 1];

        float acc[4] = {0.f, 0.f, 0.f, 0.f};

        int i = s;
        for (; i + 8 <= e; i += 8) {
            int2  cv[8];
            uint2 v[8];
            #pragma unroll
            for (int u = 0; u < 8; u++) cv[u] = g_edges[i + u];
            #pragma unroll
            for (int u = 0; u < 8; u++)
                v[u] = __ldg((const uint2*)(support + (size_t)cv[u].x * F_OUT + coff) + lane);
            #pragma unroll
            for (int u = 0; u < 8; u++)
                acc_edge2(acc, v[u], __int_as_float(cv[u].y));
        }
        for (; i + 4 <= e; i += 4) {
            int2  cv[4];
            uint2 v[4];
            #pragma unroll
            for (int u = 0; u < 4; u++) cv[u] = g_edges[i + u];
            #pragma unroll
            for (int u = 0; u < 4; u++)
                v[u] = __ldg((const uint2*)(support + (size_t)cv[u].x * F_OUT + coff) + lane);
            #pragma unroll
            for (int u = 0; u < 4; u++)
                acc_edge2(acc, v[u], __int_as_float(cv[u].y));
        }
        for (; i < e; i++) {
            int2 cv = g_edges[i];
            uint2 v = __ldg((const uint2*)(support + (size_t)cv.x * F_OUT + coff) + lane);
            acc_edge2(acc, v, __int_as_float(cv.y));
        }

        float4 o;
        o.x = __fdiv_rn(rintf(acc[0] * 1000.0f), 1000.0f) + bi.x;
        o.y = __fdiv_rn(rintf(acc[1] * 1000.0f), 1000.0f) + bi.y;
        o.z = __fdiv_rn(rintf(acc[2] * 1000.0f), 1000.0f) + bi.z;
        o.w = __fdiv_rn(rintf(acc[3] * 1000.0f), 1000.0f) + bi.w;

        *(float4*)(out + (size_t)w * F_OUT + coff + lane * 4) = o;
    }
}

// ---------------------------------------------------------------------------
// Launch — R10 schedule + A/W pre-conversion:
//   main: convW, convA -> GEMM(cols 0-127) -> GEMM(cols 128-255) -> CSR(128-255)
//   s1:   CSR build chain (overlaps the conversions + GEMM0)
//   s2:   CSR(cols 0-127) overlapping GEMM(cols 128-255)
// ---------------------------------------------------------------------------
extern "C" void kernel_launch(void* const* d_in, const int* in_sizes, int n_in,
                              void* d_out, int out_size) {
    const float* x        = (const float*)d_in[0];
    const float* weight   = (const float*)d_in[1];
    const float* bias     = (const float*)d_in[2];
    const float* edge_val = (const float*)d_in[3];
    const int*   row      = (const int*)d_in[4];
    const int*   col      = (const int*)d_in[5];
    float*       out      = (float*)d_out;

    const int N = in_sizes[0] / F_IN;
    const int E = in_sizes[3];

    __half *support, *ah, *wh;
    cudaGetSymbolAddress((void**)&support, g_supportH);
    cudaGetSymbolAddress((void**)&ah, g_Ah);
    cudaGetSymbolAddress((void**)&wh, g_Wh);
    int* count_ptr;
    cudaGetSymbolAddress((void**)&count_ptr, g_count);

    static cudaStream_t s1 = nullptr, s2 = nullptr;
    static cudaEvent_t ev_fork = nullptr, ev_join = nullptr;
    static cudaEvent_t ev_g0 = nullptr, ev_c0 = nullptr;
    static bool init_done = false;
    if (!init_done) {
        cudaStreamCreateWithFlags(&s1, cudaStreamNonBlocking);
        cudaStreamCreateWithFlags(&s2, cudaStreamNonBlocking);
        cudaEventCreateWithFlags(&ev_fork, cudaEventDisableTiming);
        cudaEventCreateWithFlags(&ev_join, cudaEventDisableTiming);
        cudaEventCreateWithFlags(&ev_g0, cudaEventDisableTiming);
        cudaEventCreateWithFlags(&ev_c0, cudaEventDisableTiming);
        init_done = true;
    }

    const int eblocks    = (E + 255) / 256;
    const int csr_blocks = (N * 32 + 255) / 256;   // full warp-per-row grid
    const dim3 gemm_grid(1, (N + 127) / 128);

    // fork: CSR build chain on s1 (overlaps conversions + GEMM0)
    cudaEventRecord(ev_fork, 0);
    cudaStreamWaitEvent(s1, ev_fork, 0);

    cudaMemsetAsync(count_ptr, 0, (size_t)N * sizeof(int), s1);
    gcn_hist_kernel<<<eblocks, 256, 0, s1>>>(row, E);
    gcn_scan_kernel<<<1, 1024, 0, s1>>>(N);
    gcn_scatter_kernel<<<eblocks, 256, 0, s1>>>(row, col, edge_val, E);
    cudaEventRecord(ev_join, s1);

    // fp16 conversions on main (A is 205->102 MB, ~50 us, hidden vs build chain)
    {
        int w4 = F_IN * F_OUT / 4;
        gcn_conv_kernel<<<(w4 + 255) / 256, 256>>>(weight, wh, w4);
        int a4 = (int)(((size_t)N * F_IN) / 4);
        gcn_conv_kernel<<<(a4 + 255) / 256, 256>>>(x, ah, a4);
    }

    // GEMM halves on main
    gcn_mma_gemm<<<gemm_grid, 256>>>(ah, wh, support, N, 0);
    cudaEventRecord(ev_g0, 0);

    gcn_mma_gemm<<<gemm_grid, 256>>>(ah, wh, support, N, 128);

    // CSR half 0 on s2: needs GEMM0 + sorted edges; overlaps GEMM1
    cudaStreamWaitEvent(s2, ev_g0, 0);
    cudaStreamWaitEvent(s2, ev_join, 0);
    gcn_csr_kernel<<<csr_blocks, 256, 0, s2>>>(support, bias, out, N, 0);
    cudaEventRecord(ev_c0, s2);

    // CSR half 1 on main: needs GEMM1 (stream order) + sorted edges
    cudaStreamWaitEvent(0, ev_join, 0);
    gcn_csr_kernel<<<csr_blocks, 256>>>(support, bias, out, N, 128);

    // join s2 back into main
    cudaStreamWaitEvent(0, ev_c0, 0);
}